// round 12
// baseline (speedup 1.0000x reference)
#include <cuda_runtime.h>
#include <cuda_fp16.h>
#include <cstdint>

#define BATCH 4
#define SEQ   1024
#define DIMC  1024
#define HEADS 16
#define HD    64

// ---------------- helpers ----------------
__device__ __forceinline__ uint32_t smem_u32(const void* p) {
    uint32_t a;
    asm("{ .reg .u64 t; cvta.to.shared.u64 t, %1; cvt.u32.u64 %0, t; }" : "=r"(a) : "l"(p));
    return a;
}
__device__ __forceinline__ void cpa16(uint32_t dst, const void* src) {
    asm volatile("cp.async.cg.shared.global [%0], [%1], 16;" :: "r"(dst), "l"(src));
}
#define CP_COMMIT() asm volatile("cp.async.commit_group;" ::: "memory")
#define CP_WAIT(n)  asm volatile("cp.async.wait_group %0;" :: "n"(n) : "memory")

#define MMA_F16(acc, a0, a1, a2, a3, b0, b1) \
    asm volatile("mma.sync.aligned.m16n8k16.row.col.f32.f16.f16.f32 " \
        "{%0,%1,%2,%3}, {%4,%5,%6,%7}, {%8,%9}, {%0,%1,%2,%3};" \
        : "+f"((acc)[0]), "+f"((acc)[1]), "+f"((acc)[2]), "+f"((acc)[3]) \
        : "r"(a0), "r"(a1), "r"(a2), "r"(a3), "r"(b0), "r"(b1))

__device__ __forceinline__ uint32_t pkh2(float lo, float hi) {
    __half2 h = __float22half2_rn(make_float2(lo, hi));
    return *(uint32_t*)&h;
}

// ---------------- scratch (fp16) ----------------
__device__ __align__(16) __half g_qkvh [(size_t)BATCH*SEQ*3*DIMC];
__device__ __align__(16) __half g_xh   [(size_t)BATCH*SEQ*DIMC];
__device__ __align__(16) __half g_wqkvh[(size_t)3*DIMC*DIMC];
__device__ __align__(16) __half g_wprojh[(size_t)DIMC*DIMC];
__device__ __align__(16) __half g_erh  [(size_t)SEQ*HD];
__device__ __align__(16) __half g_attnh[(size_t)BATCH*SEQ*DIMC];

// ---------------- fused fp32 -> fp16 conversion (all 4 inputs, one launch) ----------------
__global__ void conv_all(const float* __restrict__ x, const float* __restrict__ wqkv,
                         const float* __restrict__ wproj, const float* __restrict__ er,
                         __half* __restrict__ xh, __half* __restrict__ wqkvh,
                         __half* __restrict__ wprojh, __half* __restrict__ erh)
{
    const long T0 = (long)BATCH*SEQ*DIMC;
    const long T1 = T0 + (long)3*DIMC*DIMC;
    const long T2 = T1 + (long)DIMC*DIMC;
    const long T3 = T2 + (long)SEQ*HD;
    long i = ((long)blockIdx.x * blockDim.x + threadIdx.x) * 8;
    const float* src; __half* dst; long off;
    if      (i < T0) { src = x;     dst = xh;     off = i; }
    else if (i < T1) { src = wqkv;  dst = wqkvh;  off = i - T0; }
    else if (i < T2) { src = wproj; dst = wprojh; off = i - T1; }
    else if (i < T3) { src = er;    dst = erh;    off = i - T2; }
    else return;
    float4 v0 = *(const float4*)(src + off);
    float4 v1 = *(const float4*)(src + off + 4);
    uint4 o = { pkh2(v0.x, v0.y), pkh2(v0.z, v0.w), pkh2(v1.x, v1.y), pkh2(v1.z, v1.w) };
    *(uint4*)(dst + off) = o;
}

// ---------------- fp16 mma.sync GEMM: R10-proven (3-stage, single-sync) ----------------
#define HW 36
#define HTILE_WORDS (128*HW)
#define GSMEM_BYTES (3*2*HTILE_WORDS*4)   // 110592

template<bool OUT_HALF>
__global__ __launch_bounds__(256, 2)
void h16_gemm(const __half* __restrict__ A, const __half* __restrict__ B,
              void* __restrict__ Cv, const float* __restrict__ bias, int K, int ldc)
{
    extern __shared__ __align__(16) uint32_t smw[];
    const int tid = threadIdx.x, w = tid >> 5, t = tid & 31;
    const int m0 = blockIdx.x * 128, n0 = blockIdx.y * 128;
    const int wm = (w >> 2) * 64, wn = (w & 3) * 32;
    const int g = t >> 2, th = t & 3;

    float acc[4][4][4];
#pragma unroll
    for (int mt = 0; mt < 4; mt++)
#pragma unroll
        for (int nt = 0; nt < 4; nt++)
#pragma unroll
            for (int r = 0; r < 4; r++) acc[mt][nt][r] = 0.0f;

    const int lr = tid >> 3;
    const int lh = (tid & 7) * 8;
    const int lw = (tid & 7) * 4;

#define PREFETCH(kt, s) do {                                                   \
        uint32_t* As_ = smw + (s) * 2 * HTILE_WORDS;                           \
        uint32_t* Bs_ = As_ + HTILE_WORDS;                                     \
        const __half* Ag_ = A + (size_t)(m0) * K + (kt) * 64;                  \
        const __half* Bg_ = B + (size_t)(n0) * K + (kt) * 64;                  \
        _Pragma("unroll")                                                      \
        for (int p_ = 0; p_ < 4; p_++) {                                       \
            int r_ = p_ * 32 + lr;                                             \
            cpa16(smem_u32(&As_[r_ * HW + lw]), Ag_ + (size_t)r_ * K + lh);    \
            cpa16(smem_u32(&Bs_[r_ * HW + lw]), Bg_ + (size_t)r_ * K + lh);    \
        }                                                                      \
    } while (0)

    const int NT = K >> 6;
    PREFETCH(0, 0);
    CP_COMMIT();
    if (NT > 1) { PREFETCH(1, 1); CP_COMMIT(); }

    for (int kt = 0; kt < NT; kt++) {
        if (kt + 1 < NT) CP_WAIT(1); else CP_WAIT(0);
        __syncthreads();
        if (kt + 2 < NT) { PREFETCH(kt + 2, (kt + 2) % 3); CP_COMMIT(); }

        const uint32_t* Asu = smw + (kt % 3) * 2 * HTILE_WORDS;
        const uint32_t* Bsu = Asu + HTILE_WORDS;
#pragma unroll
        for (int ks = 0; ks < 4; ks++) {
            const int kw = ks * 8;
            uint32_t af[4][4], bf[4][2];
#pragma unroll
            for (int mt = 0; mt < 4; mt++) {
                int rb = wm + mt * 16 + g;
                af[mt][0] = Asu[rb * HW + kw + th];
                af[mt][1] = Asu[(rb + 8) * HW + kw + th];
                af[mt][2] = Asu[rb * HW + kw + th + 4];
                af[mt][3] = Asu[(rb + 8) * HW + kw + th + 4];
            }
#pragma unroll
            for (int nt = 0; nt < 4; nt++) {
                int rb = wn + nt * 8 + g;
                bf[nt][0] = Bsu[rb * HW + kw + th];
                bf[nt][1] = Bsu[rb * HW + kw + th + 4];
            }
#pragma unroll
            for (int mt = 0; mt < 4; mt++)
#pragma unroll
                for (int nt = 0; nt < 4; nt++)
                    MMA_F16(acc[mt][nt], af[mt][0], af[mt][1], af[mt][2], af[mt][3],
                            bf[nt][0], bf[nt][1]);
        }
    }
#undef PREFETCH

#pragma unroll
    for (int mt = 0; mt < 4; mt++) {
        const int row = m0 + wm + mt * 16 + g;
#pragma unroll
        for (int nt = 0; nt < 4; nt++) {
            const int col = n0 + wn + nt * 8 + 2 * th;
            if (OUT_HALF) {
                __half* C = (__half*)Cv;
                *(uint32_t*)&C[(size_t)row * ldc + col]       = pkh2(acc[mt][nt][0], acc[mt][nt][1]);
                *(uint32_t*)&C[(size_t)(row + 8) * ldc + col] = pkh2(acc[mt][nt][2], acc[mt][nt][3]);
            } else {
                float* C = (float*)Cv;
                float2 v0 = make_float2(acc[mt][nt][0], acc[mt][nt][1]);
                float2 v1 = make_float2(acc[mt][nt][2], acc[mt][nt][3]);
                if (bias) {
                    float b0 = bias[col], b1 = bias[col + 1];
                    v0.x += b0; v0.y += b1; v1.x += b0; v1.y += b1;
                }
                *(float2*)&C[(size_t)row * ldc + col]       = v0;
                *(float2*)&C[(size_t)(row + 8) * ldc + col] = v1;
            }
        }
    }
}

// ---------------- flash5: flash3 + E ring buffer + cp.async K/E prefetch ----------------
// E'[jw] = Er[EBk - jw], EBk = 1087 - i0 + 64*kt. Ring slot = ei & 255 (256 slots);
// per tile only 64 new rows load; K double-buffered; both prefetched one tile ahead.
#define FLK 0
#define FLV (2*64*36)              // 4608
#define FLE (FLV + 64*36)          // 6912
#define FLR (FLE + 256*36)         // 16128
#define FL_WORDS (FLR + 8*16*84)   // 26880
#define FL_SMEM_BYTES (FL_WORDS*4) // 107520

__global__ __launch_bounds__(256, 2)
void flash5_kernel(const __half* __restrict__ qkv, const __half* __restrict__ Erh,
                   __half* __restrict__ attn)
{
    extern __shared__ __align__(16) uint32_t smw[];
    uint32_t* Kb    = smw + FLK;          // [2] x 64 x 36w
    uint32_t* Vtm   = smw + FLV;          // Vt[d][kv] 64 x 36w
    uint32_t* Ering = smw + FLE;          // 256 slots x 36w
    float*    Rst   = (float*)(smw + FLR);// 8 x 16 x 84 (also Q staging)

    const int tid = threadIdx.x;
    const int w = tid >> 5, lane = tid & 31;
    const int qr = lane >> 2, qc = lane & 3;
    const int z = blockIdx.x;
    const int b = z >> 4, h = z & 15;
    const int i0 = (7 - (int)blockIdx.y) * 128;   // heavy q-tiles first
    const int ntiles = (i0 >> 6) + 2;

    const __half* qg = qkv + (size_t)b * SEQ * (3*DIMC) + h * HD;
    const __half* kg = qg + DIMC;
    const __half* vg = qg + 2*DIMC;

    float* Rwf = Rst + w * (16*84);

    // ---- stage Q tile, load persistent A-frags ----
    {
        uint32_t* Qs = (uint32_t*)Rst;
#pragma unroll
        for (int s = 0; s < 4; s++) {
            int idx = tid + (s << 8);
            int row = idx >> 3, w4 = (idx & 7) * 4;
            uint4 t = *(const uint4*)(qg + (size_t)(i0 + row) * (3*DIMC) + w4*2);
            *(uint4*)&Qs[row * 36 + w4] = t;
        }
    }
    __syncthreads();
    uint32_t qa[4][4];
    {
        const uint32_t* Qs = (const uint32_t*)Rst;
        const int ro = (16*w + qr) * 36 + qc;
        const int r8 = ro + 8*36;
#pragma unroll
        for (int ks = 0; ks < 4; ks++) {
            qa[ks][0] = Qs[ro + 8*ks];
            qa[ks][1] = Qs[r8 + 8*ks];
            qa[ks][2] = Qs[ro + 8*ks + 4];
            qa[ks][3] = Qs[r8 + 8*ks + 4];
        }
    }
    __syncthreads();   // Q frags read; Rst free for R staging

    // ---- prologue: cp.async prefill E window for tile 0 (192 rows) + K0 ----
    const int EB0 = 1087 - i0;
    {
#pragma unroll
        for (int s = 0; s < 6; s++) {
            int c = tid + (s << 8);            // 0..1535
            int r = c >> 3, ck = c & 7;        // row 0..191, chunk 0..7
            int ei = EB0 - 191 + r;            // >= 0 always
            int slot = ei & 255;
            int eic = ei > 1023 ? 1023 : ei;
            cpa16(smem_u32(&Ering[slot*36 + ck*4]), Erh + (size_t)eic * HD + ck*8);
        }
#pragma unroll
        for (int s = 0; s < 2; s++) {
            int c = tid + (s << 8);
            int row = c >> 3, ck = c & 7;
            cpa16(smem_u32(&Kb[row*36 + ck*4]), kg + (size_t)row * (3*DIMC) + ck*8);
        }
        CP_COMMIT();
    }

    float oa[8][4];
#pragma unroll
    for (int nf = 0; nf < 8; nf++) { oa[nf][0]=0.f; oa[nf][1]=0.f; oa[nf][2]=0.f; oa[nf][3]=0.f; }
    float mA = -1e30f, mB = -1e30f, lA = 0.f, lB = 0.f;
    const int rowA = i0 + 16*w + qr;
    const int rowB = rowA + 8;
    const float SC = 0.18033688011112042f;   // 0.125 * log2(e)

    for (int kt = 0; kt < ntiles; kt++) {
        const int kt0 = kt << 6;
        const int EBk = EB0 + kt0;
        CP_WAIT(0);          // K(kt) + E(kt) landed (issued one full tile ago)
        __syncthreads();     // all warps done with previous compute (V/K/E reads)

        // ---- prefetch K(kt+1) + E's 64 new rows for tile kt+1 ----
        if (kt + 1 < ntiles) {
            const uint32_t kbn = (uint32_t)(((kt + 1) & 1) * 2304);
#pragma unroll
            for (int s = 0; s < 2; s++) {
                int c = tid + (s << 8);
                int row = c >> 3, ck = c & 7;
                cpa16(smem_u32(&Kb[kbn + row*36 + ck*4]),
                      kg + (size_t)(kt0 + 64 + row) * (3*DIMC) + ck*8);
            }
#pragma unroll
            for (int s = 0; s < 2; s++) {
                int c = tid + (s << 8);
                int r = c >> 3, ck = c & 7;   // r 0..63
                int ei = EBk + 1 + r;
                int slot = ei & 255;
                int eic = ei > 1023 ? 1023 : ei;
                cpa16(smem_u32(&Ering[slot*36 + ck*4]), Erh + (size_t)eic * HD + ck*8);
            }
        }
        CP_COMMIT();

        // ---- V tile transposed (scalar; only blocking load left) ----
        {
            __half* Vth = (__half*)Vtm;
#pragma unroll
            for (int s = 0; s < 2; s++) {
                int idx = tid + (s << 8);
                int row = idx >> 3, d0 = (idx & 7) * 8;
                uint4 t = *(const uint4*)(vg + (size_t)(kt0 + row) * (3*DIMC) + d0);
                const __half* hp = (const __half*)&t;
#pragma unroll
                for (int j = 0; j < 8; j++) Vth[(d0 + j) * 72 + row] = hp[j];
            }
        }
        __syncthreads();

        const uint32_t* Ku = Kb + (kt & 1) * 2304;

        // ---- S = Q K^T ----
        float sacc[8][4];
#pragma unroll
        for (int nf = 0; nf < 8; nf++) { sacc[nf][0]=0.f; sacc[nf][1]=0.f; sacc[nf][2]=0.f; sacc[nf][3]=0.f; }
#pragma unroll
        for (int ks = 0; ks < 4; ks++)
#pragma unroll
            for (int nf = 0; nf < 8; nf++) {
                uint32_t b0 = Ku[(8*nf + qr)*36 + 8*ks + qc];
                uint32_t b1 = Ku[(8*nf + qr)*36 + 8*ks + qc + 4];
                MMA_F16(sacc[nf], qa[ks][0], qa[ks][1], qa[ks][2], qa[ks][3], b0, b1);
            }

        // ---- R = Q E'^T (ring-indexed rows), two 5-block halves ----
        const int esub = EBk - 16*w - qr;   // slot base for this lane
#pragma unroll
        for (int hv = 0; hv < 2; hv++) {
            float racc[5][4];
#pragma unroll
            for (int j = 0; j < 5; j++) { racc[j][0]=0.f; racc[j][1]=0.f; racc[j][2]=0.f; racc[j][3]=0.f; }
#pragma unroll
            for (int ks = 0; ks < 4; ks++)
#pragma unroll
                for (int j = 0; j < 5; j++) {
                    int jj = hv*5 + j;
                    int slot = (esub - 8*jj) & 255;
                    uint32_t b0 = Ering[slot*36 + 8*ks + qc];
                    uint32_t b1 = Ering[slot*36 + 8*ks + qc + 4];
                    MMA_F16(racc[j], qa[ks][0], qa[ks][1], qa[ks][2], qa[ks][3], b0, b1);
                }
#pragma unroll
            for (int j = 0; j < 5; j++) {
                int cb = 8*(hv*5 + j) + 2*qc;
                Rwf[qr*84 + cb]         = racc[j][0];
                Rwf[qr*84 + cb + 1]     = racc[j][1];
                Rwf[(qr+8)*84 + cb]     = racc[j][2];
                Rwf[(qr+8)*84 + cb + 1] = racc[j][3];
            }
        }
        __syncwarp();

        // ---- combine + mask (log2-scaled) ----
#pragma unroll
        for (int nf = 0; nf < 8; nf++) {
            int c0 = 8*nf + 2*qc;
            int jA = qr - c0 + 64;
            float rA0 = Rwf[qr*84 + jA];
            float rA1 = Rwf[qr*84 + jA - 1];
            float rB0 = Rwf[(qr+8)*84 + jA + 8];
            float rB1 = Rwf[(qr+8)*84 + jA + 7];
            int mg = kt0 + c0;
            sacc[nf][0] = (mg     <= rowA) ? (sacc[nf][0] + rA0) * SC : -1e30f;
            sacc[nf][1] = (mg + 1 <= rowA) ? (sacc[nf][1] + rA1) * SC : -1e30f;
            sacc[nf][2] = (mg     <= rowB) ? (sacc[nf][2] + rB0) * SC : -1e30f;
            sacc[nf][3] = (mg + 1 <= rowB) ? (sacc[nf][3] + rB1) * SC : -1e30f;
        }

        // ---- online softmax (quad shfl) ----
        float tmA = -1e30f, tmB = -1e30f;
#pragma unroll
        for (int nf = 0; nf < 8; nf++) {
            tmA = fmaxf(tmA, fmaxf(sacc[nf][0], sacc[nf][1]));
            tmB = fmaxf(tmB, fmaxf(sacc[nf][2], sacc[nf][3]));
        }
        tmA = fmaxf(tmA, __shfl_xor_sync(0xffffffffu, tmA, 1));
        tmA = fmaxf(tmA, __shfl_xor_sync(0xffffffffu, tmA, 2));
        tmB = fmaxf(tmB, __shfl_xor_sync(0xffffffffu, tmB, 1));
        tmB = fmaxf(tmB, __shfl_xor_sync(0xffffffffu, tmB, 2));
        float nmA = fmaxf(mA, tmA), nmB = fmaxf(mB, tmB);
        float aAs = exp2f(mA - nmA), aBs = exp2f(mB - nmB);
        mA = nmA; mB = nmB;

        float sA = 0.f, sB = 0.f;
#pragma unroll
        for (int nf = 0; nf < 8; nf++) {
            sacc[nf][0] = exp2f(sacc[nf][0] - mA);
            sacc[nf][1] = exp2f(sacc[nf][1] - mA);
            sacc[nf][2] = exp2f(sacc[nf][2] - mB);
            sacc[nf][3] = exp2f(sacc[nf][3] - mB);
            sA += sacc[nf][0] + sacc[nf][1];
            sB += sacc[nf][2] + sacc[nf][3];
            oa[nf][0] *= aAs; oa[nf][1] *= aAs;
            oa[nf][2] *= aBs; oa[nf][3] *= aBs;
        }
        sA += __shfl_xor_sync(0xffffffffu, sA, 1);
        sA += __shfl_xor_sync(0xffffffffu, sA, 2);
        sB += __shfl_xor_sync(0xffffffffu, sB, 1);
        sB += __shfl_xor_sync(0xffffffffu, sB, 2);
        lA = lA * aAs + sA;
        lB = lB * aBs + sB;

        // ---- O += P V : P repacked to fp16 A-frags in registers ----
#pragma unroll
        for (int ks = 0; ks < 4; ks++) {
            uint32_t p0 = pkh2(sacc[2*ks][0],   sacc[2*ks][1]);
            uint32_t p1 = pkh2(sacc[2*ks][2],   sacc[2*ks][3]);
            uint32_t p2 = pkh2(sacc[2*ks+1][0], sacc[2*ks+1][1]);
            uint32_t p3 = pkh2(sacc[2*ks+1][2], sacc[2*ks+1][3]);
#pragma unroll
            for (int nf = 0; nf < 8; nf++) {
                uint32_t b0 = Vtm[(8*nf + qr)*36 + 8*ks + qc];
                uint32_t b1 = Vtm[(8*nf + qr)*36 + 8*ks + qc + 4];
                MMA_F16(oa[nf], p0, p1, p2, p3, b0, b1);
            }
        }
    }

    // ---- epilogue: normalize, write fp16 attn ----
    const float invA = 1.f / lA, invB = 1.f / lB;
#pragma unroll
    for (int nf = 0; nf < 8; nf++) {
        int d = h*HD + 8*nf + 2*qc;
        *(uint32_t*)&attn[((size_t)b*SEQ + rowA)*DIMC + d] = pkh2(oa[nf][0]*invA, oa[nf][1]*invA);
        *(uint32_t*)&attn[((size_t)b*SEQ + rowB)*DIMC + d] = pkh2(oa[nf][2]*invB, oa[nf][3]*invB);
    }
}

// ---------------- launch ----------------
extern "C" void kernel_launch(void* const* d_in, const int* in_sizes, int n_in,
                              void* d_out, int out_size)
{
    const float* x     = (const float*)d_in[0];
    const float* Wqkv  = (const float*)d_in[1];
    const float* Wproj = (const float*)d_in[2];
    const float* bproj = (const float*)d_in[3];
    const float* Er    = (const float*)d_in[4];
    float* out = (float*)d_out;

    __half *qkvh, *xh, *wqkvh, *wprojh, *erh, *attnh;
    cudaGetSymbolAddress((void**)&qkvh,  g_qkvh);
    cudaGetSymbolAddress((void**)&xh,    g_xh);
    cudaGetSymbolAddress((void**)&wqkvh, g_wqkvh);
    cudaGetSymbolAddress((void**)&wprojh,g_wprojh);
    cudaGetSymbolAddress((void**)&erh,   g_erh);
    cudaGetSymbolAddress((void**)&attnh, g_attnh);

    cudaFuncSetAttribute(h16_gemm<true>,  cudaFuncAttributeMaxDynamicSharedMemorySize, GSMEM_BYTES);
    cudaFuncSetAttribute(h16_gemm<false>, cudaFuncAttributeMaxDynamicSharedMemorySize, GSMEM_BYTES);
    cudaFuncSetAttribute(flash5_kernel,   cudaFuncAttributeMaxDynamicSharedMemorySize, FL_SMEM_BYTES);

    // 1) all fp16 conversions in one launch
    conv_all<<<4128, 256>>>(x, Wqkv, Wproj, Er, xh, wqkvh, wprojh, erh);

    // 2) qkv = x @ Wqkv^T  (M=4096, N=3072, K=1024), fp16 out
    h16_gemm<true><<<dim3(32, 24), 256, GSMEM_BYTES>>>(xh, wqkvh, qkvh, nullptr, DIMC, 3*DIMC);

    // 3) fp16 flash attention (E-ring + cp.async prefetch)
    flash5_kernel<<<dim3(64, 8), 256, FL_SMEM_BYTES>>>(qkvh, erh, attnh);

    // 4) out = attn @ Wproj^T + b  (M=4096, N=1024, K=1024), fp32 out
    h16_gemm<false><<<dim3(32, 8), 256, GSMEM_BYTES>>>(attnh, wprojh, out, bproj, DIMC, DIMC);
}

// round 13
// speedup vs baseline: 1.1525x; 1.1525x over previous
#include <cuda_runtime.h>
#include <cuda_fp16.h>
#include <cstdint>

#define BATCH 4
#define SEQ   1024
#define DIMC  1024
#define HEADS 16
#define HD    64

// ---------------- helpers ----------------
__device__ __forceinline__ uint32_t smem_u32(const void* p) {
    uint32_t a;
    asm("{ .reg .u64 t; cvta.to.shared.u64 t, %1; cvt.u32.u64 %0, t; }" : "=r"(a) : "l"(p));
    return a;
}
__device__ __forceinline__ void cpa16(uint32_t dst, const void* src) {
    asm volatile("cp.async.cg.shared.global [%0], [%1], 16;" :: "r"(dst), "l"(src));
}
#define CP_COMMIT() asm volatile("cp.async.commit_group;" ::: "memory")
#define CP_WAIT(n)  asm volatile("cp.async.wait_group %0;" :: "n"(n) : "memory")

#define MMA_F16(acc, a0, a1, a2, a3, b0, b1) \
    asm volatile("mma.sync.aligned.m16n8k16.row.col.f32.f16.f16.f32 " \
        "{%0,%1,%2,%3}, {%4,%5,%6,%7}, {%8,%9}, {%0,%1,%2,%3};" \
        : "+f"((acc)[0]), "+f"((acc)[1]), "+f"((acc)[2]), "+f"((acc)[3]) \
        : "r"(a0), "r"(a1), "r"(a2), "r"(a3), "r"(b0), "r"(b1))

#define LDMX4T(r0, r1, r2, r3, a) \
    asm volatile("ldmatrix.sync.aligned.m8n8.x4.trans.shared.b16 {%0,%1,%2,%3}, [%4];" \
        : "=r"(r0), "=r"(r1), "=r"(r2), "=r"(r3) : "r"(a))

__device__ __forceinline__ uint32_t pkh2(float lo, float hi) {
    __half2 h = __float22half2_rn(make_float2(lo, hi));
    return *(uint32_t*)&h;
}

// ---------------- scratch (fp16) ----------------
__device__ __align__(16) __half g_qkvh [(size_t)BATCH*SEQ*3*DIMC];
__device__ __align__(16) __half g_xh   [(size_t)BATCH*SEQ*DIMC];
__device__ __align__(16) __half g_wqkvh[(size_t)3*DIMC*DIMC];
__device__ __align__(16) __half g_wprojh[(size_t)DIMC*DIMC];
__device__ __align__(16) __half g_erh  [(size_t)SEQ*HD];
__device__ __align__(16) __half g_attnh[(size_t)BATCH*SEQ*DIMC];

// ---------------- fused fp32 -> fp16 conversion (all 4 inputs, one launch) ----------------
__global__ void conv_all(const float* __restrict__ x, const float* __restrict__ wqkv,
                         const float* __restrict__ wproj, const float* __restrict__ er,
                         __half* __restrict__ xh, __half* __restrict__ wqkvh,
                         __half* __restrict__ wprojh, __half* __restrict__ erh)
{
    const long T0 = (long)BATCH*SEQ*DIMC;
    const long T1 = T0 + (long)3*DIMC*DIMC;
    const long T2 = T1 + (long)DIMC*DIMC;
    const long T3 = T2 + (long)SEQ*HD;
    long i = ((long)blockIdx.x * blockDim.x + threadIdx.x) * 8;
    const float* src; __half* dst; long off;
    if      (i < T0) { src = x;     dst = xh;     off = i; }
    else if (i < T1) { src = wqkv;  dst = wqkvh;  off = i - T0; }
    else if (i < T2) { src = wproj; dst = wprojh; off = i - T1; }
    else if (i < T3) { src = er;    dst = erh;    off = i - T2; }
    else return;
    float4 v0 = *(const float4*)(src + off);
    float4 v1 = *(const float4*)(src + off + 4);
    uint4 o = { pkh2(v0.x, v0.y), pkh2(v0.z, v0.w), pkh2(v1.x, v1.y), pkh2(v1.z, v1.w) };
    *(uint4*)(dst + off) = o;
}

// ---------------- fp16 mma.sync GEMM: R10-proven (3-stage, single-sync) ----------------
#define HW 36
#define HTILE_WORDS (128*HW)
#define GSMEM_BYTES (3*2*HTILE_WORDS*4)   // 110592

template<bool OUT_HALF>
__global__ __launch_bounds__(256, 2)
void h16_gemm(const __half* __restrict__ A, const __half* __restrict__ B,
              void* __restrict__ Cv, const float* __restrict__ bias, int K, int ldc)
{
    extern __shared__ __align__(16) uint32_t smw[];
    const int tid = threadIdx.x, w = tid >> 5, t = tid & 31;
    const int m0 = blockIdx.x * 128, n0 = blockIdx.y * 128;
    const int wm = (w >> 2) * 64, wn = (w & 3) * 32;
    const int g = t >> 2, th = t & 3;

    float acc[4][4][4];
#pragma unroll
    for (int mt = 0; mt < 4; mt++)
#pragma unroll
        for (int nt = 0; nt < 4; nt++)
#pragma unroll
            for (int r = 0; r < 4; r++) acc[mt][nt][r] = 0.0f;

    const int lr = tid >> 3;
    const int lh = (tid & 7) * 8;
    const int lw = (tid & 7) * 4;

#define PREFETCH(kt, s) do {                                                   \
        uint32_t* As_ = smw + (s) * 2 * HTILE_WORDS;                           \
        uint32_t* Bs_ = As_ + HTILE_WORDS;                                     \
        const __half* Ag_ = A + (size_t)(m0) * K + (kt) * 64;                  \
        const __half* Bg_ = B + (size_t)(n0) * K + (kt) * 64;                  \
        _Pragma("unroll")                                                      \
        for (int p_ = 0; p_ < 4; p_++) {                                       \
            int r_ = p_ * 32 + lr;                                             \
            cpa16(smem_u32(&As_[r_ * HW + lw]), Ag_ + (size_t)r_ * K + lh);    \
            cpa16(smem_u32(&Bs_[r_ * HW + lw]), Bg_ + (size_t)r_ * K + lh);    \
        }                                                                      \
    } while (0)

    const int NT = K >> 6;
    PREFETCH(0, 0);
    CP_COMMIT();
    if (NT > 1) { PREFETCH(1, 1); CP_COMMIT(); }

    for (int kt = 0; kt < NT; kt++) {
        if (kt + 1 < NT) CP_WAIT(1); else CP_WAIT(0);
        __syncthreads();
        if (kt + 2 < NT) { PREFETCH(kt + 2, (kt + 2) % 3); CP_COMMIT(); }

        const uint32_t* Asu = smw + (kt % 3) * 2 * HTILE_WORDS;
        const uint32_t* Bsu = Asu + HTILE_WORDS;
#pragma unroll
        for (int ks = 0; ks < 4; ks++) {
            const int kw = ks * 8;
            uint32_t af[4][4], bf[4][2];
#pragma unroll
            for (int mt = 0; mt < 4; mt++) {
                int rb = wm + mt * 16 + g;
                af[mt][0] = Asu[rb * HW + kw + th];
                af[mt][1] = Asu[(rb + 8) * HW + kw + th];
                af[mt][2] = Asu[rb * HW + kw + th + 4];
                af[mt][3] = Asu[(rb + 8) * HW + kw + th + 4];
            }
#pragma unroll
            for (int nt = 0; nt < 4; nt++) {
                int rb = wn + nt * 8 + g;
                bf[nt][0] = Bsu[rb * HW + kw + th];
                bf[nt][1] = Bsu[rb * HW + kw + th + 4];
            }
#pragma unroll
            for (int mt = 0; mt < 4; mt++)
#pragma unroll
                for (int nt = 0; nt < 4; nt++)
                    MMA_F16(acc[mt][nt], af[mt][0], af[mt][1], af[mt][2], af[mt][3],
                            bf[nt][0], bf[nt][1]);
        }
    }
#undef PREFETCH

#pragma unroll
    for (int mt = 0; mt < 4; mt++) {
        const int row = m0 + wm + mt * 16 + g;
#pragma unroll
        for (int nt = 0; nt < 4; nt++) {
            const int col = n0 + wn + nt * 8 + 2 * th;
            if (OUT_HALF) {
                __half* C = (__half*)Cv;
                *(uint32_t*)&C[(size_t)row * ldc + col]       = pkh2(acc[mt][nt][0], acc[mt][nt][1]);
                *(uint32_t*)&C[(size_t)(row + 8) * ldc + col] = pkh2(acc[mt][nt][2], acc[mt][nt][3]);
            } else {
                float* C = (float*)Cv;
                float2 v0 = make_float2(acc[mt][nt][0], acc[mt][nt][1]);
                float2 v1 = make_float2(acc[mt][nt][2], acc[mt][nt][3]);
                if (bias) {
                    float b0 = bias[col], b1 = bias[col + 1];
                    v0.x += b0; v0.y += b1; v1.x += b0; v1.y += b1;
                }
                *(float2*)&C[(size_t)row * ldc + col]       = v0;
                *(float2*)&C[(size_t)(row + 8) * ldc + col] = v1;
            }
        }
    }
}

// ---------------- flash6: R10 flash3 with V row-major + ldmatrix.trans PV ----------------
#define FLK 0
#define FLV (64*36)
#define FLE (FLV + 64*36)
#define FLR (FLE + 192*36)
#define FL_WORDS (FLR + 8*16*84)
#define FL_SMEM_BYTES (FL_WORDS*4)   // 89088

__global__ __launch_bounds__(256, 2)
void flash6_kernel(const __half* __restrict__ qkv, const __half* __restrict__ Erh,
                   __half* __restrict__ attn)
{
    extern __shared__ __align__(16) uint32_t smw[];
    uint32_t* Ksm = smw + FLK;          // K[kv][d] 64 x 36w
    uint32_t* Vsm = smw + FLV;          // V[kv][d] 64 x 36w (row-major, ldmatrix.trans)
    uint32_t* Esm = smw + FLE;          // E'[j][d] 192 x 36w
    float*    Rst = (float*)(smw + FLR);// 8 x 16 x 84 (also Q staging)

    const int tid = threadIdx.x;
    const int w = tid >> 5, lane = tid & 31;
    const int qr = lane >> 2, qc = lane & 3;
    const int mat = lane >> 3, mrow = lane & 7;
    const int r8 = (mat & 1) * 8 + mrow;
    const int c4 = (mat >> 1) * 4;
    const int z = blockIdx.x;
    const int b = z >> 4, h = z & 15;
    const int i0 = (7 - (int)blockIdx.y) * 128;   // heavy q-tiles first
    const int ntiles = (i0 >> 6) + 2;

    const __half* qg = qkv + (size_t)b * SEQ * (3*DIMC) + h * HD;
    const __half* kg = qg + DIMC;
    const __half* vg = qg + 2*DIMC;

    float* Rwf = Rst + w * (16*84);
    const uint32_t Vadr = smem_u32(Vsm) + (uint32_t)((r8 * 36 + c4) * 4);

    // ---- stage Q tile (fp16 copy), load persistent A-frags ----
    {
        uint32_t* Qs = (uint32_t*)Rst;
#pragma unroll
        for (int s = 0; s < 4; s++) {
            int idx = tid + (s << 8);
            int row = idx >> 3, w4 = (idx & 7) * 4;
            uint4 t = *(const uint4*)(qg + (size_t)(i0 + row) * (3*DIMC) + w4*2);
            *(uint4*)&Qs[row * 36 + w4] = t;
        }
    }
    __syncthreads();
    uint32_t qa[4][4];
    {
        const uint32_t* Qs = (const uint32_t*)Rst;
        const int ro = (16*w + qr) * 36 + qc;
        const int r8q = ro + 8*36;
#pragma unroll
        for (int ks = 0; ks < 4; ks++) {
            qa[ks][0] = Qs[ro + 8*ks];
            qa[ks][1] = Qs[r8q + 8*ks];
            qa[ks][2] = Qs[ro + 8*ks + 4];
            qa[ks][3] = Qs[r8q + 8*ks + 4];
        }
    }
    __syncthreads();

    float oa[8][4];
#pragma unroll
    for (int nf = 0; nf < 8; nf++) { oa[nf][0]=0.f; oa[nf][1]=0.f; oa[nf][2]=0.f; oa[nf][3]=0.f; }
    float mA = -1e30f, mB = -1e30f, lA = 0.f, lB = 0.f;
    const int rowA = i0 + 16*w + qr;
    const int rowB = rowA + 8;
    const float SC = 0.18033688011112042f;   // 0.125 * log2(e)

    for (int kt = 0; kt < ntiles; kt++) {
        const int kt0 = kt << 6;
        __syncthreads();

        // K and V tiles: direct fp16 uint4 copies (both row-major, conflict-free)
#pragma unroll
        for (int s = 0; s < 2; s++) {
            int idx = tid + (s << 8);
            int row = idx >> 3, w4 = (idx & 7) * 4;
            uint4 t = *(const uint4*)(kg + (size_t)(kt0 + row) * (3*DIMC) + w4*2);
            *(uint4*)&Ksm[row * 36 + w4] = t;
            uint4 u = *(const uint4*)(vg + (size_t)(kt0 + row) * (3*DIMC) + w4*2);
            *(uint4*)&Vsm[row * 36 + w4] = u;
        }
        // Er window: row jw -> Er[1087 - i0 + kt0 - jw] (clamped; invalid masked later)
        const int ebase = 1087 - i0 + kt0;
#pragma unroll
        for (int s = 0; s < 6; s++) {
            int idx = tid + (s << 8);
            int row = idx >> 3, w4 = (idx & 7) * 4;
            int ei = ebase - row;
            ei = ei < 0 ? 0 : (ei > 1023 ? 1023 : ei);
            uint4 t = *(const uint4*)(Erh + (size_t)ei * HD + w4*2);
            *(uint4*)&Esm[row * 36 + w4] = t;
        }
        __syncthreads();

        // ---- S = Q K^T ----
        float sacc[8][4];
#pragma unroll
        for (int nf = 0; nf < 8; nf++) { sacc[nf][0]=0.f; sacc[nf][1]=0.f; sacc[nf][2]=0.f; sacc[nf][3]=0.f; }
#pragma unroll
        for (int ks = 0; ks < 4; ks++)
#pragma unroll
            for (int nf = 0; nf < 8; nf++) {
                uint32_t b0 = Ksm[(8*nf + qr)*36 + 8*ks + qc];
                uint32_t b1 = Ksm[(8*nf + qr)*36 + 8*ks + qc + 4];
                MMA_F16(sacc[nf], qa[ks][0], qa[ks][1], qa[ks][2], qa[ks][3], b0, b1);
            }

        // ---- R = Q E'^T (80-wide band), two 5-block halves to cap registers ----
#pragma unroll
        for (int hv = 0; hv < 2; hv++) {
            float racc[5][4];
#pragma unroll
            for (int j = 0; j < 5; j++) { racc[j][0]=0.f; racc[j][1]=0.f; racc[j][2]=0.f; racc[j][3]=0.f; }
#pragma unroll
            for (int ks = 0; ks < 4; ks++)
#pragma unroll
                for (int j = 0; j < 5; j++) {
                    int jj = hv*5 + j;
                    uint32_t b0 = Esm[(16*w + 8*jj + qr)*36 + 8*ks + qc];
                    uint32_t b1 = Esm[(16*w + 8*jj + qr)*36 + 8*ks + qc + 4];
                    MMA_F16(racc[j], qa[ks][0], qa[ks][1], qa[ks][2], qa[ks][3], b0, b1);
                }
#pragma unroll
            for (int j = 0; j < 5; j++) {
                int cb = 8*(hv*5 + j) + 2*qc;
                Rwf[qr*84 + cb]         = racc[j][0];
                Rwf[qr*84 + cb + 1]     = racc[j][1];
                Rwf[(qr+8)*84 + cb]     = racc[j][2];
                Rwf[(qr+8)*84 + cb + 1] = racc[j][3];
            }
        }
        __syncwarp();

        // ---- combine + mask (log2-scaled) ----
#pragma unroll
        for (int nf = 0; nf < 8; nf++) {
            int c0 = 8*nf + 2*qc;
            int jA = qr - c0 + 64;
            float rA0 = Rwf[qr*84 + jA];
            float rA1 = Rwf[qr*84 + jA - 1];
            float rB0 = Rwf[(qr+8)*84 + jA + 8];
            float rB1 = Rwf[(qr+8)*84 + jA + 7];
            int mg = kt0 + c0;
            sacc[nf][0] = (mg     <= rowA) ? (sacc[nf][0] + rA0) * SC : -1e30f;
            sacc[nf][1] = (mg + 1 <= rowA) ? (sacc[nf][1] + rA1) * SC : -1e30f;
            sacc[nf][2] = (mg     <= rowB) ? (sacc[nf][2] + rB0) * SC : -1e30f;
            sacc[nf][3] = (mg + 1 <= rowB) ? (sacc[nf][3] + rB1) * SC : -1e30f;
        }

        // ---- online softmax (quad shfl) ----
        float tmA = -1e30f, tmB = -1e30f;
#pragma unroll
        for (int nf = 0; nf < 8; nf++) {
            tmA = fmaxf(tmA, fmaxf(sacc[nf][0], sacc[nf][1]));
            tmB = fmaxf(tmB, fmaxf(sacc[nf][2], sacc[nf][3]));
        }
        tmA = fmaxf(tmA, __shfl_xor_sync(0xffffffffu, tmA, 1));
        tmA = fmaxf(tmA, __shfl_xor_sync(0xffffffffu, tmA, 2));
        tmB = fmaxf(tmB, __shfl_xor_sync(0xffffffffu, tmB, 1));
        tmB = fmaxf(tmB, __shfl_xor_sync(0xffffffffu, tmB, 2));
        float nmA = fmaxf(mA, tmA), nmB = fmaxf(mB, tmB);
        float aAs = exp2f(mA - nmA), aBs = exp2f(mB - nmB);
        mA = nmA; mB = nmB;

        float sA = 0.f, sB = 0.f;
#pragma unroll
        for (int nf = 0; nf < 8; nf++) {
            sacc[nf][0] = exp2f(sacc[nf][0] - mA);
            sacc[nf][1] = exp2f(sacc[nf][1] - mA);
            sacc[nf][2] = exp2f(sacc[nf][2] - mB);
            sacc[nf][3] = exp2f(sacc[nf][3] - mB);
            sA += sacc[nf][0] + sacc[nf][1];
            sB += sacc[nf][2] + sacc[nf][3];
            oa[nf][0] *= aAs; oa[nf][1] *= aAs;
            oa[nf][2] *= aBs; oa[nf][3] *= aBs;
        }
        sA += __shfl_xor_sync(0xffffffffu, sA, 1);
        sA += __shfl_xor_sync(0xffffffffu, sA, 2);
        sB += __shfl_xor_sync(0xffffffffu, sB, 1);
        sB += __shfl_xor_sync(0xffffffffu, sB, 2);
        lA = lA * aAs + sA;
        lB = lB * aBs + sB;

        // ---- O += P V : P repacked in registers; V B-frags via ldmatrix.trans ----
#pragma unroll
        for (int ks = 0; ks < 4; ks++) {
            uint32_t p0 = pkh2(sacc[2*ks][0],   sacc[2*ks][1]);
            uint32_t p1 = pkh2(sacc[2*ks][2],   sacc[2*ks][3]);
            uint32_t p2 = pkh2(sacc[2*ks+1][0], sacc[2*ks+1][1]);
            uint32_t p3 = pkh2(sacc[2*ks+1][2], sacc[2*ks+1][3]);
#pragma unroll
            for (int nfp = 0; nfp < 4; nfp++) {
                uint32_t ra, rb, rc, rd;
                LDMX4T(ra, rb, rc, rd, Vadr + (uint32_t)(((ks * 16 * 36) + nfp * 8) * 4));
                MMA_F16(oa[2*nfp],   p0, p1, p2, p3, ra, rb);
                MMA_F16(oa[2*nfp+1], p0, p1, p2, p3, rc, rd);
            }
        }
    }

    // ---- epilogue: normalize, write fp16 attn ----
    const float invA = 1.f / lA, invB = 1.f / lB;
#pragma unroll
    for (int nf = 0; nf < 8; nf++) {
        int d = h*HD + 8*nf + 2*qc;
        *(uint32_t*)&attn[((size_t)b*SEQ + rowA)*DIMC + d] = pkh2(oa[nf][0]*invA, oa[nf][1]*invA);
        *(uint32_t*)&attn[((size_t)b*SEQ + rowB)*DIMC + d] = pkh2(oa[nf][2]*invB, oa[nf][3]*invB);
    }
}

// ---------------- launch ----------------
extern "C" void kernel_launch(void* const* d_in, const int* in_sizes, int n_in,
                              void* d_out, int out_size)
{
    const float* x     = (const float*)d_in[0];
    const float* Wqkv  = (const float*)d_in[1];
    const float* Wproj = (const float*)d_in[2];
    const float* bproj = (const float*)d_in[3];
    const float* Er    = (const float*)d_in[4];
    float* out = (float*)d_out;

    __half *qkvh, *xh, *wqkvh, *wprojh, *erh, *attnh;
    cudaGetSymbolAddress((void**)&qkvh,  g_qkvh);
    cudaGetSymbolAddress((void**)&xh,    g_xh);
    cudaGetSymbolAddress((void**)&wqkvh, g_wqkvh);
    cudaGetSymbolAddress((void**)&wprojh,g_wprojh);
    cudaGetSymbolAddress((void**)&erh,   g_erh);
    cudaGetSymbolAddress((void**)&attnh, g_attnh);

    cudaFuncSetAttribute(h16_gemm<true>,  cudaFuncAttributeMaxDynamicSharedMemorySize, GSMEM_BYTES);
    cudaFuncSetAttribute(h16_gemm<false>, cudaFuncAttributeMaxDynamicSharedMemorySize, GSMEM_BYTES);
    cudaFuncSetAttribute(flash6_kernel,   cudaFuncAttributeMaxDynamicSharedMemorySize, FL_SMEM_BYTES);

    // 1) all fp16 conversions in one launch
    conv_all<<<4128, 256>>>(x, Wqkv, Wproj, Er, xh, wqkvh, wprojh, erh);

    // 2) qkv = x @ Wqkv^T  (M=4096, N=3072, K=1024), fp16 out
    h16_gemm<true><<<dim3(32, 24), 256, GSMEM_BYTES>>>(xh, wqkvh, qkvh, nullptr, DIMC, 3*DIMC);

    // 3) fp16 flash attention (V row-major + ldmatrix.trans PV)
    flash6_kernel<<<dim3(64, 8), 256, FL_SMEM_BYTES>>>(qkvh, erh, attnh);

    // 4) out = attn @ Wproj^T + b  (M=4096, N=1024, K=1024), fp32 out
    h16_gemm<false><<<dim3(32, 8), 256, GSMEM_BYTES>>>(attnh, wprojh, out, bproj, DIMC, DIMC);
}